// round 1
// baseline (speedup 1.0000x reference)
#include <cuda_runtime.h>
#include <math.h>

// Problem constants: N=20000, NUM_COEF=25, C=H=O=S=64, 2H=128, LMAX=4
#define NTH 256

__device__ __constant__ int c_deg[25] = {
    0, 1,1,1, 2,2,2,2,2, 3,3,3,3,3,3,3, 4,4,4,4,4,4,4,4,4
};
// bw[m] = 1/((2l+1)*LMAX) for row m>=1 with l=deg[m]
__device__ __constant__ float c_bw[25] = {
    0.f,
    1.f/12.f, 1.f/12.f, 1.f/12.f,
    1.f/20.f, 1.f/20.f, 1.f/20.f, 1.f/20.f, 1.f/20.f,
    1.f/28.f, 1.f/28.f, 1.f/28.f, 1.f/28.f, 1.f/28.f, 1.f/28.f, 1.f/28.f,
    1.f/36.f, 1.f/36.f, 1.f/36.f, 1.f/36.f, 1.f/36.f, 1.f/36.f, 1.f/36.f, 1.f/36.f, 1.f/36.f
};

__device__ __forceinline__ float silu_f(float v) {
    return v * (1.f / (1.f + __expf(-v)));
}

// Shared memory layout (floats):
//  sxn : 1600  (xn, 25x64)
//  sh  : 1600  (h, later hb+gating, 25x64)
//  sg  : 4096  (g, later g3, 64x64)
//  sg1 : 8192  (64x128)
//  sg2 : 8192  (64x128)
//  stg : 1600  (to_grid 64x25)
//  sgat:   64
//  sred:   32
// total 25376 floats = 101504 bytes -> 2 CTAs/SM
#define SMEM_FLOATS 25376

__global__ __launch_bounds__(NTH, 2)
void fused_equi(
    const float* __restrict__ x,
    const float* __restrict__ nl0w,
    const float* __restrict__ nl0b,
    const float* __restrict__ affw,
    const float* __restrict__ l1w,
    const float* __restrict__ l1b,
    const float* __restrict__ scw,
    const float* __restrict__ scb,
    const float* __restrict__ gw1,
    const float* __restrict__ gw2,
    const float* __restrict__ gw3,
    const float* __restrict__ l2w,
    const float* __restrict__ l2b,
    const float* __restrict__ tg,
    float* __restrict__ out)
{
    extern __shared__ float smf[];
    float* sxn  = smf;
    float* sh   = sxn + 1600;
    float* sg   = sh  + 1600;
    float* sg1  = sg  + 4096;
    float* sg2  = sg1 + 8192;
    float* stg  = sg2 + 8192;
    float* sgat = stg + 1600;
    float* sred = sgat + 64;

    const int tid = threadIdx.x;
    const long long n = blockIdx.x;
    const float* xin = x + n * 1600;

    // ---- load x and to_grid ----
    for (int i = tid; i < 1600; i += NTH) { sxn[i] = xin[i]; stg[i] = tg[i]; }
    __syncthreads();

    // ---- stats: L0 layernorm (mu, var) + weighted fnorm for L>0 ----
    float s0 = 0.f, q0 = 0.f, fn = 0.f;
    for (int i = tid; i < 1600; i += NTH) {
        float v = sxn[i];
        int m = i >> 6;
        if (m == 0) { s0 += v; q0 += v * v; }
        else        { fn += c_bw[m] * v * v; }
    }
    #pragma unroll
    for (int off = 16; off > 0; off >>= 1) {
        s0 += __shfl_xor_sync(0xffffffffu, s0, off);
        q0 += __shfl_xor_sync(0xffffffffu, q0, off);
        fn += __shfl_xor_sync(0xffffffffu, fn, off);
    }
    const int wid = tid >> 5, lane = tid & 31;
    if (lane == 0) { sred[wid] = s0; sred[8 + wid] = q0; sred[16 + wid] = fn; }
    __syncthreads();
    if (tid == 0) {
        float a = 0.f, b = 0.f, c = 0.f;
        #pragma unroll
        for (int w = 0; w < 8; w++) { a += sred[w]; b += sred[8 + w]; c += sred[16 + w]; }
        float mu  = a * (1.f / 64.f);
        float var = b * (1.f / 64.f) - mu * mu;
        sred[24] = mu;
        sred[25] = rsqrtf(var + 1e-5f);
        sred[26] = rsqrtf(c * (1.f / 64.f) + 1e-5f);
    }
    __syncthreads();
    const float mu = sred[24], rstd = sred[25], inv = sred[26];

    // ---- normalize in place ----
    for (int i = tid; i < 1600; i += NTH) {
        int m = i >> 6, cc = i & 63;
        float v = sxn[i];
        if (m == 0) v = (v - mu) * rstd * nl0w[cc] + nl0b[cc];
        else        v = v * inv * affw[(c_deg[m] - 1) * 64 + cc];
        sxn[i] = v;
    }
    __syncthreads();

    // ---- gating = silu(x0n @ scalar_w + scalar_b)  (threads 0..63) ----
    if (tid < 64) {
        float acc = scb[tid];
        #pragma unroll 8
        for (int i = 0; i < 64; i++) acc += sxn[i] * scw[i * 64 + tid];
        sgat[tid] = silu_f(acc);
    }

    // ---- h[m,o] = xn[m,:] @ lin1_w[deg[m]]  (+ lin1_b at m=0) ----
    {
        const int j = tid & 63, grp = tid >> 6;
        for (int l = 0; l < 5; l++) {
            const int base = l * l, cnt = 2 * l + 1;
            const int r0 = base + grp, r1 = r0 + 4, r2 = r1 + 4;
            const bool b0 = grp < cnt, b1 = grp + 4 < cnt, b2 = grp + 8 < cnt;
            float a0 = 0.f, a1 = 0.f, a2 = 0.f;
            const float* w = l1w + l * 4096 + j;
            #pragma unroll 8
            for (int i = 0; i < 64; i++) {
                float wv = w[i * 64];
                if (b0) a0 += sxn[r0 * 64 + i] * wv;
                if (b1) a1 += sxn[r1 * 64 + i] * wv;
                if (b2) a2 += sxn[r2 * 64 + i] * wv;
            }
            if (b0) sh[r0 * 64 + j] = a0 + (r0 == 0 ? l1b[j] : 0.f);
            if (b1) sh[r1 * 64 + j] = a1;
            if (b2) sh[r2 * 64 + j] = a2;
        }
    }
    __syncthreads();

    // ---- g[s,c] = sum_m tg[s,m] * h[m,c]   (64x64, k=25) ----
    {
        const int ty = tid >> 4, tx = tid & 15;
        float acc[4][4] = {};
        for (int m = 0; m < 25; m++) {
            float4 hv = *reinterpret_cast<const float4*>(sh + m * 64 + tx * 4);
            float tv[4];
            #pragma unroll
            for (int r = 0; r < 4; r++) tv[r] = stg[(ty * 4 + r) * 25 + m];
            #pragma unroll
            for (int r = 0; r < 4; r++) {
                acc[r][0] += tv[r] * hv.x;
                acc[r][1] += tv[r] * hv.y;
                acc[r][2] += tv[r] * hv.z;
                acc[r][3] += tv[r] * hv.w;
            }
        }
        #pragma unroll
        for (int r = 0; r < 4; r++)
            *reinterpret_cast<float4*>(sg + (ty * 4 + r) * 64 + tx * 4) =
                make_float4(acc[r][0], acc[r][1], acc[r][2], acc[r][3]);
    }
    __syncthreads();

    // ---- g1 = silu(g @ W1)  (64x128, k=64) ----
    {
        const int ty = tid >> 4, tx = tid & 15;
        float acc[4][8] = {};
        for (int k = 0; k < 64; k++) {
            float a[4];
            #pragma unroll
            for (int r = 0; r < 4; r++) a[r] = sg[(ty * 4 + r) * 64 + k];
            float4 w0 = *reinterpret_cast<const float4*>(gw1 + k * 128 + tx * 8);
            float4 w1 = *reinterpret_cast<const float4*>(gw1 + k * 128 + tx * 8 + 4);
            float b[8] = {w0.x, w0.y, w0.z, w0.w, w1.x, w1.y, w1.z, w1.w};
            #pragma unroll
            for (int r = 0; r < 4; r++)
                #pragma unroll
                for (int q = 0; q < 8; q++) acc[r][q] += a[r] * b[q];
        }
        #pragma unroll
        for (int r = 0; r < 4; r++) {
            float4 o0 = make_float4(silu_f(acc[r][0]), silu_f(acc[r][1]), silu_f(acc[r][2]), silu_f(acc[r][3]));
            float4 o1 = make_float4(silu_f(acc[r][4]), silu_f(acc[r][5]), silu_f(acc[r][6]), silu_f(acc[r][7]));
            *reinterpret_cast<float4*>(sg1 + (ty * 4 + r) * 128 + tx * 8)     = o0;
            *reinterpret_cast<float4*>(sg1 + (ty * 4 + r) * 128 + tx * 8 + 4) = o1;
        }
    }
    __syncthreads();

    // ---- g2 = silu(g1 @ W2)  (64x128, k=128) ----
    {
        const int ty = tid >> 4, tx = tid & 15;
        float acc[4][8] = {};
        for (int k = 0; k < 128; k++) {
            float a[4];
            #pragma unroll
            for (int r = 0; r < 4; r++) a[r] = sg1[(ty * 4 + r) * 128 + k];
            float4 w0 = *reinterpret_cast<const float4*>(gw2 + k * 128 + tx * 8);
            float4 w1 = *reinterpret_cast<const float4*>(gw2 + k * 128 + tx * 8 + 4);
            float b[8] = {w0.x, w0.y, w0.z, w0.w, w1.x, w1.y, w1.z, w1.w};
            #pragma unroll
            for (int r = 0; r < 4; r++)
                #pragma unroll
                for (int q = 0; q < 8; q++) acc[r][q] += a[r] * b[q];
        }
        #pragma unroll
        for (int r = 0; r < 4; r++) {
            float4 o0 = make_float4(silu_f(acc[r][0]), silu_f(acc[r][1]), silu_f(acc[r][2]), silu_f(acc[r][3]));
            float4 o1 = make_float4(silu_f(acc[r][4]), silu_f(acc[r][5]), silu_f(acc[r][6]), silu_f(acc[r][7]));
            *reinterpret_cast<float4*>(sg2 + (ty * 4 + r) * 128 + tx * 8)     = o0;
            *reinterpret_cast<float4*>(sg2 + (ty * 4 + r) * 128 + tx * 8 + 4) = o1;
        }
    }
    __syncthreads();

    // ---- g3 = g2 @ W3  (64x64, k=128) -> reuse sg ----
    {
        const int ty = tid >> 4, tx = tid & 15;
        float acc[4][4] = {};
        for (int k = 0; k < 128; k++) {
            float a[4];
            #pragma unroll
            for (int r = 0; r < 4; r++) a[r] = sg2[(ty * 4 + r) * 128 + k];
            float4 w = *reinterpret_cast<const float4*>(gw3 + k * 64 + tx * 4);
            #pragma unroll
            for (int r = 0; r < 4; r++) {
                acc[r][0] += a[r] * w.x;
                acc[r][1] += a[r] * w.y;
                acc[r][2] += a[r] * w.z;
                acc[r][3] += a[r] * w.w;
            }
        }
        #pragma unroll
        for (int r = 0; r < 4; r++)
            *reinterpret_cast<float4*>(sg + (ty * 4 + r) * 64 + tx * 4) =
                make_float4(acc[r][0], acc[r][1], acc[r][2], acc[r][3]);
    }
    __syncthreads();

    // ---- hb[m,c] = sum_s tg[s,m] * g3[s,c], m=1..24; row 0 <- gating ----
    {
        const int j = tid & 63, grp = tid >> 6;
        float acc[6] = {};
        for (int s = 0; s < 64; s++) {
            float gv = sg[s * 64 + j];
            #pragma unroll
            for (int r = 0; r < 6; r++)
                acc[r] += stg[s * 25 + 1 + grp + 4 * r] * gv;
        }
        #pragma unroll
        for (int r = 0; r < 6; r++) sh[(1 + grp + 4 * r) * 64 + j] = acc[r];
    }
    if (tid < 64) sh[tid] = sgat[tid];
    __syncthreads();

    // ---- out[m,o] = h_final[m,:] @ lin2_w[deg[m]]  (+ lin2_b at m=0) ----
    {
        const int j = tid & 63, grp = tid >> 6;
        float* outn = out + n * 1600;
        for (int l = 0; l < 5; l++) {
            const int base = l * l, cnt = 2 * l + 1;
            const int r0 = base + grp, r1 = r0 + 4, r2 = r1 + 4;
            const bool b0 = grp < cnt, b1 = grp + 4 < cnt, b2 = grp + 8 < cnt;
            float a0 = 0.f, a1 = 0.f, a2 = 0.f;
            const float* w = l2w + l * 4096 + j;
            #pragma unroll 8
            for (int i = 0; i < 64; i++) {
                float wv = w[i * 64];
                if (b0) a0 += sh[r0 * 64 + i] * wv;
                if (b1) a1 += sh[r1 * 64 + i] * wv;
                if (b2) a2 += sh[r2 * 64 + i] * wv;
            }
            if (b0) outn[r0 * 64 + j] = a0 + (r0 == 0 ? l2b[j] : 0.f);
            if (b1) outn[r1 * 64 + j] = a1;
            if (b2) outn[r2 * 64 + j] = a2;
        }
    }
}

extern "C" void kernel_launch(void* const* d_in, const int* in_sizes, int n_in,
                              void* d_out, int out_size)
{
    const float* x    = (const float*)d_in[0];
    const float* nl0w = (const float*)d_in[1];
    const float* nl0b = (const float*)d_in[2];
    const float* affw = (const float*)d_in[3];
    const float* l1w  = (const float*)d_in[4];
    const float* l1b  = (const float*)d_in[5];
    const float* scw  = (const float*)d_in[6];
    const float* scb  = (const float*)d_in[7];
    const float* gw1  = (const float*)d_in[8];
    const float* gw2  = (const float*)d_in[9];
    const float* gw3  = (const float*)d_in[10];
    const float* l2w  = (const float*)d_in[11];
    const float* l2b  = (const float*)d_in[12];
    const float* tg   = (const float*)d_in[13];
    float* out = (float*)d_out;

    const int N = in_sizes[0] / 1600;   // 25*64 floats per sample
    const size_t smem = SMEM_FLOATS * sizeof(float);

    cudaFuncSetAttribute(fused_equi, cudaFuncAttributeMaxDynamicSharedMemorySize, (int)smem);
    fused_equi<<<N, NTH, smem>>>(x, nl0w, nl0b, affw, l1w, l1b, scw, scb,
                                 gw1, gw2, gw3, l2w, l2b, tg, out);
}